// round 17
// baseline (speedup 1.0000x reference)
#include <cuda_runtime.h>
#include <cuda_bf16.h>
#include <cstdint>

#define TMAX 50
#define KS 8
#define WCOLS 136          // bf16 per W row (128 + 8 pad for bank-conflict-free ldsm)
#define SB2 272            // bytes per row
#define GROWS 32           // padded rows per group
#define VROWS 28           // valid rows per group

// ---- smem layout (bytes) ----
#define W_OFF    0         // 512*272 = 139264 (aliased by MLP scratch)
#define H_OFF    139264    // 2 groups * 32 * 272 = 17408
#define OFFX_OFF 156672    // 56*50*4
#define OFFY_OFF 167872    // 56*50*4
#define BASE_OFF 179072    // 56 float2
#define OFFC_OFF 179520    // 2*28*2 floats
#define ABS_OFF  179968    // 512*3 floats (per (unit,gate): bias,a0,a1)
#define PART_OFF 186112    // 2*32*2*16 floats
#define SMEM_BYTES 202496

// ---- device-global prepped images ----
__device__ __nv_bfloat16 g_wE[512 * WCOLS];
__device__ __nv_bfloat16 g_wD[512 * WCOLS];
__device__ float g_abE[512 * 3];     // [u*12 + g*3 + {bias,a0,a1}]
__device__ float g_abD[512 * 3];
__device__ float g_Wm1T[128 * 256];
__device__ float g_Wm2T[256 * 112];

// ---- helpers ----
__device__ __forceinline__ float tanha_(float x) {
    float r; asm("tanh.approx.f32 %0,%1;" : "=f"(r) : "f"(x)); return r;
}
__device__ __forceinline__ float sigma_(float x) {
    return fmaf(0.5f, tanha_(0.5f * x), 0.5f);
}
__device__ __forceinline__ void ldsm4(uint32_t& r0, uint32_t& r1, uint32_t& r2,
                                      uint32_t& r3, uint32_t addr) {
    asm volatile("ldmatrix.sync.aligned.m8n8.x4.shared.b16 {%0,%1,%2,%3},[%4];"
                 : "=r"(r0), "=r"(r1), "=r"(r2), "=r"(r3) : "r"(addr));
}
__device__ __forceinline__ void mma4(float* d, uint32_t a0, uint32_t a1, uint32_t a2,
                                     uint32_t a3, uint32_t b0, uint32_t b1) {
    asm volatile(
        "mma.sync.aligned.m16n8k16.row.col.f32.bf16.bf16.f32 "
        "{%0,%1,%2,%3},{%4,%5,%6,%7},{%8,%9},{%0,%1,%2,%3};"
        : "+f"(d[0]), "+f"(d[1]), "+f"(d[2]), "+f"(d[3])
        : "r"(a0), "r"(a1), "r"(a2), "r"(a3), "r"(b0), "r"(b1));
}

// ---- fused precompute ----
__global__ void k_prep(const float* __restrict__ Wih_e, const float* __restrict__ We,
                       const float* __restrict__ be,   const float* __restrict__ b_e,
                       const float* __restrict__ Wih_d, const float* __restrict__ Wd,
                       const float* __restrict__ bd,   const float* __restrict__ b_d,
                       const float* __restrict__ Whh_e, const float* __restrict__ Whh_d,
                       const float* __restrict__ Wm1,  const float* __restrict__ Wm2,
                       int E)
{
    int idx0 = blockIdx.x * blockDim.x + threadIdx.x;
    int stride = gridDim.x * blockDim.x;

    // W images: plain Whh bf16, row stride WCOLS, cols 128..135 zero
    for (int i = idx0; i < 2 * 512 * WCOLS; i += stride) {
        int which = i >= 512 * WCOLS;
        int idx = which ? i - 512 * WCOLS : i;
        int gg = idx / WCOLS, k = idx % WCOLS;
        float v = (k < 128) ? (which ? Whh_d : Whh_e)[gg * 128 + k] : 0.f;
        (which ? g_wD : g_wE)[gg * WCOLS + k] = __float2bfloat16(v);
    }

    // folds: per (unit n, gate g): bias = Wih@bin + bg ; a0, a1 = Wih@Win cols
    for (int i = idx0; i < 1024; i += stride) {
        int which = i >> 9;
        int gn = i & 511;
        const float* Wih = which ? Wih_d : Wih_e;
        const float* Win = which ? Wd : We;
        const float* bin = which ? bd : be;
        const float* bg  = which ? b_d : b_e;
        float a0 = 0.f, a1 = 0.f, bb = 0.f;
        for (int e = 0; e < E; e++) {
            float wv = Wih[gn * E + e];
            a0 += wv * Win[e * 2 + 0];
            a1 += wv * Win[e * 2 + 1];
            bb += wv * bin[e];
        }
        bb += bg[gn];
        int n = gn & 127, g = gn >> 7;
        float* dst = which ? g_abD : g_abE;
        dst[n * 12 + g * 3 + 0] = bb;
        dst[n * 12 + g * 3 + 1] = a0;
        dst[n * 12 + g * 3 + 2] = a1;
    }

    for (int j = idx0; j < 128 * 256; j += stride) {
        int k = j >> 8, mc = j & 255;
        g_Wm1T[j] = Wm1[mc * 128 + k];
    }
    for (int j = idx0; j < 256 * 112; j += stride) {
        int k = j / 112, mc = j % 112;
        g_Wm2T[j] = Wm2[mc * 256 + k];
    }
}

// ---- MMA for one group: acc[(mt*4+g)*4 + idx], 32 floats ----
__device__ __forceinline__ void mma_grp(uint32_t a_base, uint32_t b01, uint32_t b23,
                                        float* acc) {
#pragma unroll
    for (int i = 0; i < 32; i++) acc[i] = 0.f;
#pragma unroll
    for (int ks = 0; ks < KS; ks++) {
        uint32_t A0[4], A1[4], Bx[8];
        ldsm4(A0[0], A0[1], A0[2], A0[3], a_base + ks * 32);
        ldsm4(A1[0], A1[1], A1[2], A1[3], a_base + 16 * SB2 + ks * 32);
        ldsm4(Bx[0], Bx[1], Bx[2], Bx[3], b01 + ks * 32);
        ldsm4(Bx[4], Bx[5], Bx[6], Bx[7], b23 + ks * 32);
#pragma unroll
        for (int g = 0; g < 4; g++) {
            mma4(&acc[(0 * 4 + g) * 4], A0[0], A0[1], A0[2], A0[3], Bx[2 * g], Bx[2 * g + 1]);
            mma4(&acc[(1 * 4 + g) * 4], A1[0], A1[1], A1[2], A1[3], Bx[2 * g], Bx[2 * g + 1]);
        }
    }
}

// ---- epilogue for one group (DEC: also Wr partials) ----
template<bool DEC>
__device__ __forceinline__ void epilogue(
    char* smem, int grp, const float* acc, float* cst,
    const float* ox_arr, const float* oy_arr,      // encoder sources (t-sliced)
    int w, int lane,
    float wr0a, float wr0b, float wr1a, float wr1b)
{
    const float* abt = (const float*)(smem + ABS_OFF);
    const int u0 = 8 * w + 2 * (lane & 3);
    char* hbase = smem + H_OFF + grp * GROWS * SB2;
#pragma unroll
    for (int mt = 0; mt < 2; mt++) {
#pragma unroll
        for (int rh = 0; rh < 2; rh++) {
            int rloc = 16 * mt + (lane >> 2) + 8 * rh;
            int rl = rloc < VROWS ? rloc : VROWS - 1;
            float ox, oy;
            if (DEC) {
                const float* oc = (const float*)(smem + OFFC_OFF) + (grp * VROWS + rl) * 2;
                ox = oc[0]; oy = oc[1];
            } else {
                ox = ox_arr[grp * VROWS + rl];
                oy = oy_arr[grp * VROWS + rl];
            }
            float hq[2];
#pragma unroll
            for (int q = 0; q < 2; q++) {
                int idx = 2 * rh + q;
                const float* ab = abt + (u0 + q) * 12;
                float pi = acc[(mt * 4 + 0) * 4 + idx] + fmaf(ab[1],  ox, fmaf(ab[2],  oy, ab[0]));
                float pf = acc[(mt * 4 + 1) * 4 + idx] + fmaf(ab[4],  ox, fmaf(ab[5],  oy, ab[3]));
                float pg = acc[(mt * 4 + 2) * 4 + idx] + fmaf(ab[7],  ox, fmaf(ab[8],  oy, ab[6]));
                float po = acc[(mt * 4 + 3) * 4 + idx] + fmaf(ab[10], ox, fmaf(ab[11], oy, ab[9]));
                int ci = mt * 4 + 2 * rh + q;
                float cn = sigma_(pf) * cst[ci] + sigma_(pi) * tanha_(pg);
                cst[ci] = cn;
                float hn = sigma_(po) * tanha_(cn);
                hq[q] = hn;
                if (rloc < VROWS)
                    *(__nv_bfloat16*)(hbase + rloc * SB2 + (u0 + q) * 2) = __float2bfloat16(hn);
            }
            if (DEC) {
                float p0 = fmaf(wr0a, hq[0], wr0b * hq[1]);
                float p1 = fmaf(wr1a, hq[0], wr1b * hq[1]);
                p0 += __shfl_xor_sync(0xffffffffu, p0, 1);
                p0 += __shfl_xor_sync(0xffffffffu, p0, 2);
                p1 += __shfl_xor_sync(0xffffffffu, p1, 1);
                p1 += __shfl_xor_sync(0xffffffffu, p1, 2);
                if ((lane & 3) == 0) {
                    float* pp = (float*)(smem + PART_OFF)
                              + ((grp * GROWS + rloc) * 2 + 0) * 16 + w;
                    pp[0]  = p0;
                    pp[16] = p1;
                }
            }
        }
    }
}

// ---- main persistent kernel: 512 threads, 56 rows/CTA (2 groups x 28) ----
__global__ void __launch_bounds__(512, 1)
k_main(const float* __restrict__ obs, const float* __restrict__ bm1,
       const float* __restrict__ bm2, const float* __restrict__ Wr,
       const float* __restrict__ br, const float* __restrict__ z,
       float* __restrict__ out, int B, int T, int S)
{
    extern __shared__ char smem[];
    const int tid = threadIdx.x;
    const int lane = tid & 31, w = tid >> 5;
    const int b0 = blockIdx.x * 2 * VROWS;
    if (T > TMAX) T = TMAX;

    uint32_t sbase = (uint32_t)__cvta_generic_to_shared(smem);
    float* offx_s = (float*)(smem + OFFX_OFF);
    float* offy_s = (float*)(smem + OFFY_OFF);
    float* base_s = (float*)(smem + BASE_OFF);     // [row56][2]
    float* offc   = (float*)(smem + OFFC_OFF);     // [g*28+row][2]
    float* abs_s  = (float*)(smem + ABS_OFF);

    // ldmatrix bases
    const uint32_t aG0 = sbase + H_OFF + (lane & 15) * SB2 + ((lane >> 4) << 4);
    const uint32_t aG1 = aG0 + GROWS * SB2;
    const uint32_t b01 = sbase + W_OFF
        + (((lane >> 4) & 1) * 128 + 8 * w + (lane & 7)) * SB2 + (((lane >> 3) & 1) << 4);
    const uint32_t b23 = b01 + 256 * SB2;

    // ---- init ----
    for (int i = tid; i < 2 * GROWS * SB2 / 4; i += 512)
        ((uint32_t*)(smem + H_OFF))[i] = 0;
    for (int i = tid; i < 1536; i += 512) abs_s[i] = g_abE[i];
    for (int i = tid; i < 2 * VROWS * T; i += 512) {
        int rr = i / T, t = i % T;
        int b = b0 + rr;
        float ox = 0.f, oy = 0.f, cx = 0.f, cy = 0.f;
        if (b < B) {
            cx = obs[((size_t)b * T + t) * 2 + 0];
            cy = obs[((size_t)b * T + t) * 2 + 1];
            float px = 0.f, py = 0.f;
            if (t > 0) {
                px = obs[((size_t)b * T + t - 1) * 2 + 0];
                py = obs[((size_t)b * T + t - 1) * 2 + 1];
            }
            ox = cx - px; oy = cy - py;
        }
        if (t == T - 1) { base_s[rr * 2] = cx; base_s[rr * 2 + 1] = cy; }
        offx_s[t * 56 + rr] = ox;
        offy_s[t * 56 + rr] = oy;
    }
    {
        const float4* src = (const float4*)g_wE;
        float4* dst = (float4*)(smem + W_OFF);
        for (int i = tid; i < 512 * WCOLS * 2 / 16; i += 512) dst[i] = src[i];
    }
    __syncthreads();

    float acc0[32], acc1[32], cst0[8], cst1[8];
#pragma unroll
    for (int i = 0; i < 8; i++) { cst0[i] = 0.f; cst1[i] = 0.f; }

    // ---- encoder (pipelined phases) ----
    mma_grp(aG0, b01, b23, acc0);
    __syncthreads();
    mma_grp(aG1, b01, b23, acc1);
    epilogue<false>(smem, 0, acc0, cst0, offx_s, offy_s, w, lane, 0, 0, 0, 0);
    __syncthreads();
    for (int t = 1; t < T; t++) {
        mma_grp(aG0, b01, b23, acc0);
        epilogue<false>(smem, 1, acc1, cst1, offx_s + (t - 1) * 56, offy_s + (t - 1) * 56,
                        w, lane, 0, 0, 0, 0);
        __syncthreads();
        mma_grp(aG1, b01, b23, acc1);
        epilogue<false>(smem, 0, acc0, cst0, offx_s + t * 56, offy_s + t * 56,
                        w, lane, 0, 0, 0, 0);
        __syncthreads();
    }
    epilogue<false>(smem, 1, acc1, cst1, offx_s + (T - 1) * 56, offy_s + (T - 1) * 56,
                    w, lane, 0, 0, 0, 0);
    __syncthreads();

    // ---- MLP (aliases W region: hf [0,28672), m1 [28672,86016)) ----
    {
        float* hf = (float*)(smem + W_OFF);
        float* m1 = (float*)(smem + W_OFF + 28672);
        for (int i = tid; i < 56 * 128; i += 512) {
            int rr = i >> 7, k = i & 127;
            int g = rr >= VROWS, rloc = rr - g * VROWS;
            hf[i] = __bfloat162float(
                *(const __nv_bfloat16*)(smem + H_OFF + (g * GROWS + rloc) * SB2 + k * 2));
        }
        __syncthreads();
        {
            int mc = tid & 255, half = tid >> 8;
            for (int rr = half * 28; rr < half * 28 + 28; rr++) {
                float acc = bm1[mc];
                const float* hr = hf + rr * 128;
#pragma unroll 8
                for (int k = 0; k < 128; k++)
                    acc = fmaf(hr[k], g_Wm1T[k * 256 + mc], acc);
                m1[rr * 256 + mc] = fmaxf(acc, 0.f);
            }
        }
        __syncthreads();
        if (tid < 448) {
            int n2 = tid % 112, rq = tid / 112;
            for (int rr = rq * 14; rr < rq * 14 + 14; rr++) {
                float acc = bm2[n2];
                const float* mr = m1 + rr * 256;
#pragma unroll 8
                for (int k = 0; k < 256; k++)
                    acc = fmaf(mr[k], g_Wm2T[k * 112 + n2], acc);
                int g = rr >= VROWS, rloc = rr - g * VROWS;
                *(__nv_bfloat16*)(smem + H_OFF + (g * GROWS + rloc) * SB2 + n2 * 2) =
                    __float2bfloat16(fmaxf(acc, 0.f));
            }
        }
        for (int i = tid; i < 56 * 16; i += 512) {
            int rr = i >> 4, zi = i & 15;
            int b = b0 + rr;
            float zv = (b < B) ? z[(size_t)b * 16 + zi] : 0.f;
            int g = rr >= VROWS, rloc = rr - g * VROWS;
            *(__nv_bfloat16*)(smem + H_OFF + (g * GROWS + rloc) * SB2 + (112 + zi) * 2) =
                __float2bfloat16(zv);
        }
        if (tid < 112) {
            int g = tid / 56, rem = tid % 56, row = rem >> 1, comp = rem & 1;
            float v = (comp ? offy_s : offx_s)[(T - 1) * 56 + g * VROWS + row];
            offc[(g * VROWS + row) * 2 + comp] = v;
        }
    }
    __syncthreads();
    // decoder W image + folds
    {
        const float4* src = (const float4*)g_wD;
        float4* dst = (float4*)(smem + W_OFF);
        for (int i = tid; i < 512 * WCOLS * 2 / 16; i += 512) dst[i] = src[i];
    }
    for (int i = tid; i < 1536; i += 512) abs_s[i] = g_abD[i];
#pragma unroll
    for (int i = 0; i < 8; i++) { cst0[i] = 0.f; cst1[i] = 0.f; }

    // decoder per-thread state
    const int u0 = 8 * w + 2 * (lane & 3);
    const float wr0a = Wr[u0], wr0b = Wr[u0 + 1];
    const float wr1a = Wr[128 + u0], wr1b = Wr[128 + u0 + 1];
    const int frow = tid >> 1, fcomp = tid & 1;
    const bool fact = (tid < 56);
    float fbase0 = 0.f, fbase1 = 0.f, foacc0 = 0.f, foacc1 = 0.f, fbr = 0.f;
    if (fact) {
        fbase0 = base_s[frow * 2 + fcomp];
        fbase1 = base_s[(VROWS + frow) * 2 + fcomp];
        fbr = br[fcomp];
    }
    __syncthreads();

    // finalize lambda-ish macro
#define FINALIZE(GRP, SS)                                                          \
    if (fact) {                                                                    \
        const float* pp = (float*)(smem + PART_OFF)                                \
                        + (((GRP) * GROWS + frow) * 2 + fcomp) * 16;               \
        float4 v0 = ((const float4*)pp)[0], v1 = ((const float4*)pp)[1];           \
        float4 v2 = ((const float4*)pp)[2], v3 = ((const float4*)pp)[3];           \
        float sum = (((v0.x + v0.y) + (v0.z + v0.w)) + ((v1.x + v1.y) + (v1.z + v1.w))) \
                  + (((v2.x + v2.y) + (v2.z + v2.w)) + ((v3.x + v3.y) + (v3.z + v3.w))); \
        float off = sum + fbr;                                                     \
        float* oa = (GRP) ? &foacc1 : &foacc0;                                     \
        *oa += off;                                                                \
        offc[((GRP) * VROWS + frow) * 2 + fcomp] = off;                            \
        int b = b0 + (GRP) * VROWS + frow;                                         \
        if (b < B)                                                                 \
            out[((size_t)b * S + (SS)) * 2 + fcomp] =                              \
                ((GRP) ? fbase1 : fbase0) + *oa;                                   \
    }

    // ---- decoder (pipelined phases) ----
    mma_grp(aG0, b01, b23, acc0);
    __syncthreads();
    mma_grp(aG1, b01, b23, acc1);
    epilogue<true>(smem, 0, acc0, cst0, 0, 0, w, lane, wr0a, wr0b, wr1a, wr1b);
    __syncthreads();
    for (int s = 1; s < S; s++) {
        mma_grp(aG0, b01, b23, acc0);
        epilogue<true>(smem, 1, acc1, cst1, 0, 0, w, lane, wr0a, wr0b, wr1a, wr1b);
        FINALIZE(0, s - 1);
        __syncthreads();
        mma_grp(aG1, b01, b23, acc1);
        epilogue<true>(smem, 0, acc0, cst0, 0, 0, w, lane, wr0a, wr0b, wr1a, wr1b);
        FINALIZE(1, s - 1);
        __syncthreads();
    }
    epilogue<true>(smem, 1, acc1, cst1, 0, 0, w, lane, wr0a, wr0b, wr1a, wr1b);
    FINALIZE(0, S - 1);
    __syncthreads();
    FINALIZE(1, S - 1);
}

// ---- launch ----
extern "C" void kernel_launch(void* const* d_in, const int* in_sizes, int n_in,
                              void* d_out, int out_size) {
    const float* obs   = (const float*)d_in[0];
    const float* We    = (const float*)d_in[2];
    const float* be    = (const float*)d_in[3];
    const float* Wih_e = (const float*)d_in[4];
    const float* Whh_e = (const float*)d_in[5];
    const float* b_e   = (const float*)d_in[6];
    const float* Wm1   = (const float*)d_in[7];
    const float* bm1   = (const float*)d_in[8];
    const float* Wm2   = (const float*)d_in[9];
    const float* bm2   = (const float*)d_in[10];
    const float* Wd    = (const float*)d_in[11];
    const float* bd    = (const float*)d_in[12];
    const float* Wih_d = (const float*)d_in[13];
    const float* Whh_d = (const float*)d_in[14];
    const float* b_d   = (const float*)d_in[15];
    const float* Wr    = (const float*)d_in[16];
    const float* br    = (const float*)d_in[17];
    const float* z     = (const float*)d_in[18];
    float* out = (float*)d_out;

    int NZ = 16;
    int B = in_sizes[18] / NZ;
    int T = in_sizes[0] / (B * 2);
    int S = out_size / (B * 2);
    int E = in_sizes[2] / 2;

    k_prep<<<256, 256>>>(Wih_e, We, be, b_e, Wih_d, Wd, bd, b_d,
                         Whh_e, Whh_d, Wm1, Wm2, E);

    cudaFuncSetAttribute(k_main, cudaFuncAttributeMaxDynamicSharedMemorySize, SMEM_BYTES);
    int grid = (B + 2 * VROWS - 1) / (2 * VROWS);
    k_main<<<grid, 512, SMEM_BYTES>>>(obs, bm1, bm2, Wr, br, z, out, B, T, S);
}